// round 5
// baseline (speedup 1.0000x reference)
#include <cuda_runtime.h>

#define BB 16
#define QQ 300
#define SNUM 16
#define HID 256
#define T_TOT 13125
#define W0 100
#define H0 100
#define QP 3
#define S_SCALE_C 0.077f
#define NBLK 192
#define NA 96                       // blocks doing phase A
#define RB 8                        // rows per A-block (96*8 = 768)
#define TILE 16                     // w1 tile: 16 input channels
#define NT (HID / TILE)             // 16 tiles
#define ITEMS (BB * QQ * SNUM)      // 76800
#define PER_BLK (ITEMS / NBLK)      // 400

__device__ __align__(16) float g_off[BB * QP * SNUM * 4];
__device__ unsigned g_cnt;          // cumulative across launches, never reset

typedef unsigned long long ull;

__device__ __forceinline__ ull pack2(float lo, float hi) {
    ull r; asm("mov.b64 %0, {%1, %2};" : "=l"(r) : "f"(lo), "f"(hi)); return r;
}
__device__ __forceinline__ void unpack2(ull v, float& lo, float& hi) {
    asm("mov.b64 {%0, %1}, %2;" : "=f"(lo), "=f"(hi) : "l"(v));
}
__device__ __forceinline__ void fma2(ull& d, ull a, ull b) {
    asm("fma.rn.f32x2 %0, %1, %2, %3;" : "=l"(d) : "l"(a), "l"(b), "l"(d));
}
__device__ __forceinline__ float tanh_fast(float x) {
    float r; asm("tanh.approx.f32 %0, %1;" : "=f"(r) : "f"(x)); return r;
}
__device__ __forceinline__ unsigned ld_cg_u32(const unsigned* p) {
    unsigned v; asm volatile("ld.global.cg.u32 %0, [%1];" : "=r"(v) : "l"(p)); return v;
}

__device__ __forceinline__ void poly_xy(const float* __restrict__ c, int s,
                                        float& spx, float& spy) {
    const float t  = (float)s * (1.0f / (float)(SNUM - 1));
    const float t2 = t * t, t3 = t2 * t;
    spx = 2.0f * (c[0] * t3 + c[1] * t2 + c[2] * t + c[3] - 0.5f);
    spy = 2.0f * (c[4] * t3 + c[5] * t2 + c[6] * t + c[7] - 0.5f);
}

__global__ __launch_bounds__(256, 2) void fused_kernel(
        const float* __restrict__ rp,
        const float* __restrict__ mem,
        const float* __restrict__ w1,
        const float* __restrict__ b1,
        const float* __restrict__ w2,
        const float* __restrict__ b2,
        const int* __restrict__ rl,
        float* __restrict__ out) {
    const int blk = blockIdx.x;
    const int tid = threadIdx.x;

    __shared__ __align__(16) float gsp[HID * RB];          // 8KB  [c][r] packed
    __shared__ __align__(16) float h1s[RB * HID];          // 8KB  gather staging, then h1
    __shared__ __align__(16) float w1s[2][TILE * HID];     // 32KB double-buffered tiles
    unsigned* tgt_slot = (unsigned*)gsp;                   // alias: gsp dead by barrier time

    const bool isA = (blk < NA);

    if (isA) {
        // ============ gather: 32 threads/row, 8 channels each (2x float4) ============
        {
            const int r = tid >> 5;            // 0..7
            const int u = tid & 31;            // channel group of 8
            const int row = blk * RB + r;      // b*48 + qp*16 + s
            const int s  = row & 15;
            const int qp = (row >> 4) % QP;
            const int b  = row / (QP * SNUM);

            float gx, gy;
            poly_xy(rp + ((size_t)b * QQ + qp) * 8, s, gx, gy);
            const float x = (gx + 1.0f) * (W0 * 0.5f) - 0.5f;
            const float y = (gy + 1.0f) * (H0 * 0.5f) - 0.5f;
            const float x0f = floorf(x), y0f = floorf(y);
            const int x0 = (int)x0f, y0 = (int)y0f;
            const float wx1 = x - x0f, wx0 = 1.0f - wx1;
            const float wy1 = y - y0f, wy0 = 1.0f - wy1;

            const float* memb = mem + (size_t)b * T_TOT * HID;
            float4 a0 = make_float4(0.f, 0.f, 0.f, 0.f);
            float4 a1 = a0;
            #pragma unroll
            for (int dy = 0; dy < 2; dy++) {
                const int yi = y0 + dy;
                if (yi < 0 || yi >= H0) continue;
                const float wy = dy ? wy1 : wy0;
                #pragma unroll
                for (int dx = 0; dx < 2; dx++) {
                    const int xi = x0 + dx;
                    if (xi < 0 || xi >= W0) continue;
                    const float wgt = wy * (dx ? wx1 : wx0);
                    const float* p = memb + (size_t)(yi * W0 + xi) * HID + u * 8;
                    const float4 v0 = __ldg(reinterpret_cast<const float4*>(p));
                    const float4 v1 = __ldg(reinterpret_cast<const float4*>(p + 4));
                    a0.x += wgt * v0.x; a0.y += wgt * v0.y;
                    a0.z += wgt * v0.z; a0.w += wgt * v0.w;
                    a1.x += wgt * v1.x; a1.y += wgt * v1.y;
                    a1.z += wgt * v1.z; a1.w += wgt * v1.w;
                }
            }
            *reinterpret_cast<float4*>(&h1s[r * HID + u * 8 + 0]) = a0;
            *reinterpret_cast<float4*>(&h1s[r * HID + u * 8 + 4]) = a1;
        }
        __syncthreads();

        // ============ transpose [r][c] -> packed [c][r] ============
        {
            float4 p0, p1;
            p0.x = h1s[0 * HID + tid]; p0.y = h1s[1 * HID + tid];
            p0.z = h1s[2 * HID + tid]; p0.w = h1s[3 * HID + tid];
            p1.x = h1s[4 * HID + tid]; p1.y = h1s[5 * HID + tid];
            p1.z = h1s[6 * HID + tid]; p1.w = h1s[7 * HID + tid];
            *reinterpret_cast<float4*>(&gsp[tid * RB + 0]) = p0;
            *reinterpret_cast<float4*>(&gsp[tid * RB + 4]) = p1;
        }

        // ============ layer 1: smem-staged w1, register-prefetch pipeline ============
        {
            const float bv = b1[tid];
            ull ac0 = pack2(bv, bv), ac1 = pack2(bv, bv);
            ull ac2 = pack2(bv, bv), ac3 = pack2(bv, bv);

            const float4* w1v = reinterpret_cast<const float4*>(w1);
            float4 nx0, nx1, nx2, nx3;
            // preload tile 0 (1024 float4 per tile, 4 per thread)
            nx0 = __ldg(&w1v[0 * 256 + tid]);
            nx1 = __ldg(&w1v[1 * 256 + tid]);
            nx2 = __ldg(&w1v[2 * 256 + tid]);
            nx3 = __ldg(&w1v[3 * 256 + tid]);
            {
                float4* dst = reinterpret_cast<float4*>(w1s[0]);
                dst[0 * 256 + tid] = nx0;
                dst[1 * 256 + tid] = nx1;
                dst[2 * 256 + tid] = nx2;
                dst[3 * 256 + tid] = nx3;
            }
            __syncthreads();

            int cur = 0;
            for (int t = 0; t < NT; t++) {
                if (t < NT - 1) {
                    const float4* src = &w1v[(t + 1) * (TILE * HID / 4)];
                    nx0 = __ldg(&src[0 * 256 + tid]);
                    nx1 = __ldg(&src[1 * 256 + tid]);
                    nx2 = __ldg(&src[2 * 256 + tid]);
                    nx3 = __ldg(&src[3 * 256 + tid]);
                }
                const float* wt = &w1s[cur][tid];
                const int cbase = t * TILE;
                #pragma unroll
                for (int cc = 0; cc < TILE; cc++) {
                    const float w = wt[cc * HID];
                    const ull wp = pack2(w, w);
                    const float* g = &gsp[(cbase + cc) * RB];
                    const ull g0 = *reinterpret_cast<const ull*>(g + 0);
                    const ull g1 = *reinterpret_cast<const ull*>(g + 2);
                    const ull g2 = *reinterpret_cast<const ull*>(g + 4);
                    const ull g3 = *reinterpret_cast<const ull*>(g + 6);
                    fma2(ac0, g0, wp);
                    fma2(ac1, g1, wp);
                    fma2(ac2, g2, wp);
                    fma2(ac3, g3, wp);
                }
                if (t < NT - 1) {
                    float4* dst = reinterpret_cast<float4*>(w1s[cur ^ 1]);
                    dst[0 * 256 + tid] = nx0;
                    dst[1 * 256 + tid] = nx1;
                    dst[2 * 256 + tid] = nx2;
                    dst[3 * 256 + tid] = nx3;
                }
                __syncthreads();
                cur ^= 1;
            }

            float v0, v1;
            unpack2(ac0, v0, v1);
            h1s[0 * HID + tid] = tanh_fast(v0); h1s[1 * HID + tid] = tanh_fast(v1);
            unpack2(ac1, v0, v1);
            h1s[2 * HID + tid] = tanh_fast(v0); h1s[3 * HID + tid] = tanh_fast(v1);
            unpack2(ac2, v0, v1);
            h1s[4 * HID + tid] = tanh_fast(v0); h1s[5 * HID + tid] = tanh_fast(v1);
            unpack2(ac3, v0, v1);
            h1s[6 * HID + tid] = tanh_fast(v0); h1s[7 * HID + tid] = tanh_fast(v1);
        }
        __syncthreads();

        // ============ layer 2: warp w = row w, 4 outputs via float4 w2 rows ============
        {
            const int wid = tid >> 5, lane = tid & 31;
            float a0 = 0.f, a1 = 0.f, a2 = 0.f, a3 = 0.f;
            const float4* w2v = reinterpret_cast<const float4*>(w2);
            #pragma unroll
            for (int j = lane; j < HID; j += 32) {
                const float h = h1s[wid * HID + j];
                const float4 wr = __ldg(&w2v[j]);
                a0 += h * wr.x; a1 += h * wr.y; a2 += h * wr.z; a3 += h * wr.w;
            }
            #pragma unroll
            for (int o = 16; o > 0; o >>= 1) {
                a0 += __shfl_xor_sync(0xffffffffu, a0, o);
                a1 += __shfl_xor_sync(0xffffffffu, a1, o);
                a2 += __shfl_xor_sync(0xffffffffu, a2, o);
                a3 += __shfl_xor_sync(0xffffffffu, a3, o);
            }
            if (lane == 0) {
                float4 ov;
                ov.x = S_SCALE_C * tanh_fast(a0 + b2[0]);
                ov.y = S_SCALE_C * tanh_fast(a1 + b2[1]);
                ov.z = S_SCALE_C * tanh_fast(a2 + b2[2]);
                ov.w = S_SCALE_C * tanh_fast(a3 + b2[3]);
                reinterpret_cast<float4*>(g_off)[blk * RB + wid] = ov;
            }
        }
        __threadfence();
        __syncthreads();      // all rows of this block written + fenced; gsp now dead
    }

    // arrive (A-blocks after producing, B-blocks immediately)
    if (tid == 0) {
        const unsigned t = atomicAdd(&g_cnt, 1u);
        *tgt_slot = t - (t % NBLK) + NBLK;
    }

    // ================= Phase B prologue (independent of g_off) ===============
    float spx[2], spy[2];
    int lvl[2], bI[2], sI[2], idxI[2];
    bool valid[2];
    #pragma unroll
    for (int p = 0; p < 2; p++) {
        const int idx = blk * PER_BLK + p * 256 + tid;
        valid[p] = (p == 0) || (tid < PER_BLK - 256);
        idxI[p] = idx;
        if (valid[p]) {
            const int s  = idx & 15;
            const int qb = idx >> 4;
            const int q  = qb % QQ;
            const int b  = qb / QQ;
            poly_xy(rp + ((size_t)b * QQ + q) * 8, s, spx[p], spy[p]);
            lvl[p] = rl[b * QQ + q];
            bI[p] = b; sI[p] = s;
        }
    }

    // ================= global barrier ======================
    __syncthreads();                         // tgt_slot visible
    if (tid == 0) {
        const unsigned tgt = *tgt_slot;
        while ((int)(ld_cg_u32(&g_cnt) - tgt) < 0)
            __nanosleep(64);
    }
    __syncthreads();
    __threadfence();                         // acquire

    // ================= epilogue: gather offsets, write ===============
    #pragma unroll
    for (int p = 0; p < 2; p++) {
        if (!valid[p]) continue;
        const float* o = g_off + (((size_t)bI[p] * QP + lvl[p]) * SNUM + sI[p]) * 4;
        const float4 ov = __ldcg(reinterpret_cast<const float4*>(o));
        float4 v;
        v.x = ov.x + spx[p];
        v.y = ov.y + spy[p];
        v.z = ov.z + spx[p];
        v.w = ov.w + spy[p];
        reinterpret_cast<float4*>(out)[idxI[p]] = v;
    }
}

extern "C" void kernel_launch(void* const* d_in, const int* in_sizes, int n_in,
                              void* d_out, int out_size) {
    const float* ref_polys = (const float*)d_in[0];
    const float* memory    = (const float*)d_in[1];
    const float* w1        = (const float*)d_in[2];
    const float* b1        = (const float*)d_in[3];
    const float* w2        = (const float*)d_in[4];
    const float* b2        = (const float*)d_in[5];
    const int*   ref_lvls  = (const int*)d_in[6];
    float* out = (float*)d_out;

    fused_kernel<<<NBLK, 256>>>(ref_polys, memory, w1, b1, w2, b2, ref_lvls, out);
}